// round 10
// baseline (speedup 1.0000x reference)
#include <cuda_runtime.h>
#include <cuda_bf16.h>
#include <cstdint>

static constexpr int N = 50000;
static constexpr int E = 1600000;
static constexpr int SCAN_B = 1024;
static constexpr int NBLK = (N + SCAN_B - 1) / SCAN_B;   // 49

// ---------------- scratch -----------------------------------------------------
__device__ __align__(16) float g_h0[N * 128];
__device__ __align__(16) float g_h1[N * 128];
__device__ __align__(16) float g_mean[N * 128];
__device__ __align__(16) __nv_bfloat16 g_bA[N * 128];   // bf16 shadows for gather
__device__ __align__(16) __nv_bfloat16 g_bB[N * 128];
__device__ __align__(16) float g_Wr0[256 * 128];        // tf32-rounded, [k][n]
__device__ __align__(16) float g_Wr1[256 * 128];
__device__ __align__(16) float g_Wr2[256 * 64];
__device__ int   g_deg[N];
__device__ int   g_row[N + 1];
__device__ int   g_fill[N];
__device__ int   g_csr[E];
__device__ float g_inv[N];
__device__ int   g_bsum[NBLK];

// cvt.rna.tf32.f32 needs a .b32 destination -> go through a uint register.
__device__ __forceinline__ float to_tf32(float x) {
    uint32_t u;
    asm("cvt.rna.tf32.f32 %0, %1;" : "=r"(u) : "f"(x));
    return __uint_as_float(u);
}
// L2-only load (skip L1 allocation; gather rows have ~0% L1 hit rate)
__device__ __forceinline__ uint2 ldcg_u2(const void* p) {
    uint2 r;
    asm volatile("ld.global.cg.v2.u32 {%0,%1}, [%2];" : "=r"(r.x), "=r"(r.y) : "l"(p));
    return r;
}

// ---------------- merged prep: zero deg + tf32 weights + bf16 features --------
__global__ void prep_all_k(const float* __restrict__ f,
                           const float* __restrict__ W0,
                           const float* __restrict__ W1,
                           const float* __restrict__ W2) {
    int i = blockIdx.x * blockDim.x + threadIdx.x;
    if (i < N * 64) {
        float2 v = ((const float2*)f)[i];
        ((__nv_bfloat162*)g_bA)[i] = __float22bfloat162_rn(v);
    }
    if (i < N) g_deg[i] = 0;
    if (i < 256 * 128) {
        g_Wr0[i] = to_tf32(W0[i]);
        g_Wr1[i] = to_tf32(W1[i]);
    }
    if (i < 256 * 64) g_Wr2[i] = to_tf32(W2[i]);
}

// ---------------- CSR build ---------------------------------------------------
// 4 edges per thread, independent atomics -> MLP=4 hides the 318-cyc ATOMG/RED
// latency (old version was MLP=1 latency-bound: issue=4.3% in ncu).
__global__ void count_k(const int* __restrict__ dst) {
    int i = blockIdx.x * blockDim.x + threadIdx.x;
    int base = i * 4;
    if (base + 3 < E) {
        int4 d = *(const int4*)(dst + base);
        atomicAdd(&g_deg[d.x], 1);
        atomicAdd(&g_deg[d.y], 1);
        atomicAdd(&g_deg[d.z], 1);
        atomicAdd(&g_deg[d.w], 1);
    } else {
        for (int e = base; e < E; e++) atomicAdd(&g_deg[dst[e]], 1);
    }
}

// block-local exclusive scan of g_deg -> g_row (no global offset); block sums
__global__ void __launch_bounds__(SCAN_B) scanA_k() {
    __shared__ int wsum[32];
    int tid = threadIdx.x, lane = tid & 31, wid = tid >> 5;
    int i = blockIdx.x * SCAN_B + tid;
    int v = (i < N) ? g_deg[i] : 0;
    int x = v;
    #pragma unroll
    for (int o = 1; o < 32; o <<= 1) {
        int t = __shfl_up_sync(0xffffffffu, x, o);
        if (lane >= o) x += t;
    }
    if (lane == 31) wsum[wid] = x;
    __syncthreads();
    if (wid == 0) {
        int s = wsum[lane];
        #pragma unroll
        for (int o = 1; o < 32; o <<= 1) {
            int t = __shfl_up_sync(0xffffffffu, s, o);
            if (lane >= o) s += t;
        }
        wsum[lane] = s;
    }
    __syncthreads();
    int excl = x - v + (wid ? wsum[wid - 1] : 0);
    if (i < N) g_row[i] = excl;
    if (tid == SCAN_B - 1) g_bsum[blockIdx.x] = wsum[31];
}

// single small block: exclusive scan of the 49 block sums; writes g_row[N]
__global__ void scanB_k() {
    __shared__ int s[NBLK];
    int tid = threadIdx.x;
    if (tid < NBLK) s[tid] = g_bsum[tid];
    __syncthreads();
    if (tid == 0) {
        int run = 0;
        for (int b = 0; b < NBLK; b++) {
            int v = s[b];
            s[b] = run;
            run += v;
        }
        g_row[N] = run;
    }
    __syncthreads();
    if (tid < NBLK) g_bsum[tid] = s[tid];
}

// add block offsets; produce fill + inv_deg
__global__ void __launch_bounds__(SCAN_B) scanC_k() {
    int i = blockIdx.x * SCAN_B + threadIdx.x;
    if (i < N) {
        int r = g_row[i] + g_bsum[blockIdx.x];
        g_row[i] = r;
        g_fill[i] = r;
        int d = g_deg[i];
        g_inv[i] = 1.0f / (float)(d > 0 ? d : 1);
    }
}

__global__ void scatter_k(const int* __restrict__ src, const int* __restrict__ dst) {
    int i = blockIdx.x * blockDim.x + threadIdx.x;
    int base = i * 4;
    if (base + 3 < E) {
        int4 d = *(const int4*)(dst + base);
        int4 s = *(const int4*)(src + base);
        int p0 = atomicAdd(&g_fill[d.x], 1);
        int p1 = atomicAdd(&g_fill[d.y], 1);
        int p2 = atomicAdd(&g_fill[d.z], 1);
        int p3 = atomicAdd(&g_fill[d.w], 1);
        g_csr[p0] = s.x;
        g_csr[p1] = s.y;
        g_csr[p2] = s.z;
        g_csr[p3] = s.w;
    } else {
        for (int e = base; e < E; e++) {
            int pos = atomicAdd(&g_fill[dst[e]], 1);
            g_csr[pos] = src[e];
        }
    }
}

// ---------------- aggregation: mean of bf16 h[src] over in-edges --------------
// One node per warp; lane covers 4 features. 16-deep unroll -> 16 outstanding
// L2 loads per dependency step. 512-thread blocks (16 warps).
__global__ void __launch_bounds__(512)
agg_k(int gat_sel) {
    const __nv_bfloat16* h = (gat_sel == 0) ? g_bA : g_bB;
    int tid = threadIdx.x, lane = tid & 31, w = tid >> 5;
    int node = blockIdx.x * 16 + w;
    if (node >= N) return;
    int k4 = lane * 4;
    float4 acc = make_float4(0.f, 0.f, 0.f, 0.f);
    int beg = g_row[node], end = g_row[node + 1];
    int e = beg;
    for (; e + 16 <= end; e += 16) {
        int s[16];
        #pragma unroll
        for (int q = 0; q < 16; q++) s[q] = g_csr[e + q];
        uint2 r[16];
        #pragma unroll
        for (int q = 0; q < 16; q++) r[q] = ldcg_u2(h + s[q] * 128 + k4);
        float x0 = 0.f, y0 = 0.f, z0 = 0.f, w0 = 0.f;
        #pragma unroll
        for (int q = 0; q < 16; q++) {
            x0 += __uint_as_float(r[q].x << 16);
            y0 += __uint_as_float(r[q].x & 0xffff0000u);
            z0 += __uint_as_float(r[q].y << 16);
            w0 += __uint_as_float(r[q].y & 0xffff0000u);
        }
        acc.x += x0; acc.y += y0; acc.z += z0; acc.w += w0;
    }
    for (; e + 4 <= end; e += 4) {
        int s[4];
        #pragma unroll
        for (int q = 0; q < 4; q++) s[q] = g_csr[e + q];
        uint2 r[4];
        #pragma unroll
        for (int q = 0; q < 4; q++) r[q] = ldcg_u2(h + s[q] * 128 + k4);
        #pragma unroll
        for (int q = 0; q < 4; q++) {
            acc.x += __uint_as_float(r[q].x << 16);
            acc.y += __uint_as_float(r[q].x & 0xffff0000u);
            acc.z += __uint_as_float(r[q].y << 16);
            acc.w += __uint_as_float(r[q].y & 0xffff0000u);
        }
    }
    for (; e < end; ++e) {
        int s = g_csr[e];
        uint2 r = ldcg_u2(h + s * 128 + k4);
        acc.x += __uint_as_float(r.x << 16);
        acc.y += __uint_as_float(r.x & 0xffff0000u);
        acc.z += __uint_as_float(r.y << 16);
        acc.w += __uint_as_float(r.y & 0xffff0000u);
    }
    float idg = g_inv[node];
    acc.x *= idg; acc.y *= idg; acc.z *= idg; acc.w *= idg;
    *(float4*)(g_mean + node * 128 + k4) = acc;
}

// ---------------- tf32 mma.sync GEMM layer ------------------------------------
template <int FOUT, bool RELU, int SHADOW>   // SHADOW: 0 none, 1 g_bB, 2 g_bA
__global__ void __launch_bounds__(256)
gemm_k(const float* __restrict__ hself_p, int self_sel,
       const float* __restrict__ bias,
       float* __restrict__ out_p, int out_sel, int wsel) {
    const float* hs = (self_sel == 0) ? hself_p : (self_sel == 1 ? g_h0 : g_h1);
    float* of = (out_sel == 0) ? out_p : (out_sel == 1 ? g_h0 : g_h1);
    const float* Wr = (wsel == 0) ? g_Wr0 : (wsel == 1 ? g_Wr1 : g_Wr2);
    __nv_bfloat16* sh = (SHADOW == 1) ? g_bB : g_bA;

    constexpr int WP = FOUT + 8;
    constexpr int AP = 132;
    constexpr int NT = FOUT / 32;
    extern __shared__ float smem[];
    float* sW = smem;                // [128][WP]
    float* sA = smem + 128 * WP;     // [64][AP]

    int tid = threadIdx.x, lane = tid & 31, w = tid >> 5;
    int g = lane >> 2, tg = lane & 3;
    int wm = w & 1, wn = w >> 1;
    int node_base = blockIdx.x * 64;

    float c[2][NT][4];
    #pragma unroll
    for (int mt = 0; mt < 2; mt++)
        #pragma unroll
        for (int nt = 0; nt < NT; nt++)
            #pragma unroll
            for (int i = 0; i < 4; i++) c[mt][nt][i] = 0.f;

    #pragma unroll
    for (int half = 0; half < 2; half++) {
        const float* srcW = Wr + half * 128 * FOUT;
        for (int idx = tid; idx < 128 * (FOUT / 4); idx += 256) {
            int k = idx / (FOUT / 4);
            int c4 = (idx % (FOUT / 4)) * 4;
            float4 v = *(const float4*)(srcW + k * FOUT + c4);
            *(float4*)(sW + k * WP + c4) = v;
        }
        const float* srcA = (half == 0) ? hs : g_mean;
        for (int idx = tid; idx < 64 * 32; idx += 256) {
            int r = idx >> 5;
            int c4 = (idx & 31) << 2;
            int node = node_base + r;
            float4 v = make_float4(0.f, 0.f, 0.f, 0.f);
            if (node < N) v = *(const float4*)(srcA + node * 128 + c4);
            v.x = to_tf32(v.x); v.y = to_tf32(v.y);
            v.z = to_tf32(v.z); v.w = to_tf32(v.w);
            *(float4*)(sA + r * AP + c4) = v;
        }
        __syncthreads();

        #pragma unroll 4
        for (int s = 0; s < 16; s++) {
            int k = s * 8;
            uint32_t a[2][4];
            #pragma unroll
            for (int mt = 0; mt < 2; mt++) {
                int r0 = wm * 32 + mt * 16 + g;
                a[mt][0] = __float_as_uint(sA[r0 * AP + k + tg]);
                a[mt][1] = __float_as_uint(sA[(r0 + 8) * AP + k + tg]);
                a[mt][2] = __float_as_uint(sA[r0 * AP + k + tg + 4]);
                a[mt][3] = __float_as_uint(sA[(r0 + 8) * AP + k + tg + 4]);
            }
            #pragma unroll
            for (int nt = 0; nt < NT; nt++) {
                int col = wn * (FOUT / 4) + nt * 8 + g;
                uint32_t b0 = __float_as_uint(sW[(k + tg) * WP + col]);
                uint32_t b1 = __float_as_uint(sW[(k + tg + 4) * WP + col]);
                #pragma unroll
                for (int mt = 0; mt < 2; mt++) {
                    asm volatile(
                        "mma.sync.aligned.m16n8k8.row.col.f32.tf32.tf32.f32 "
                        "{%0,%1,%2,%3}, {%4,%5,%6,%7}, {%8,%9}, {%0,%1,%2,%3};"
                        : "+f"(c[mt][nt][0]), "+f"(c[mt][nt][1]),
                          "+f"(c[mt][nt][2]), "+f"(c[mt][nt][3])
                        : "r"(a[mt][0]), "r"(a[mt][1]), "r"(a[mt][2]), "r"(a[mt][3]),
                          "r"(b0), "r"(b1));
                }
            }
        }
        __syncthreads();
    }

    // ---- epilogue: bias + relu + fp32 store (+ bf16 shadow) ----
    #pragma unroll
    for (int nt = 0; nt < NT; nt++) {
        int col = wn * (FOUT / 4) + nt * 8 + tg * 2;
        float bx = __ldg(bias + col), by = __ldg(bias + col + 1);
        #pragma unroll
        for (int mt = 0; mt < 2; mt++) {
            #pragma unroll
            for (int hrow = 0; hrow < 2; hrow++) {
                int node = node_base + wm * 32 + mt * 16 + g + hrow * 8;
                if (node >= N) continue;
                float ox = c[mt][nt][hrow * 2 + 0] + bx;
                float oy = c[mt][nt][hrow * 2 + 1] + by;
                if (RELU) { ox = fmaxf(ox, 0.f); oy = fmaxf(oy, 0.f); }
                *(float2*)(of + node * FOUT + col) = make_float2(ox, oy);
                if (SHADOW != 0) {
                    __nv_bfloat162 p = __float22bfloat162_rn(make_float2(ox, oy));
                    *(__nv_bfloat162*)(sh + node * 128 + col) = p;
                }
            }
        }
    }
}

// ---------------- launcher ----------------------------------------------------
extern "C" void kernel_launch(void* const* d_in, const int* in_sizes, int n_in,
                              void* d_out, int out_size) {
    const float* feat = (const float*)d_in[0];
    const int*   src  = (const int*)d_in[1];
    const int*   dst  = (const int*)d_in[2];
    const float* W0   = (const float*)d_in[3];
    const float* b0   = (const float*)d_in[4];
    const float* W1   = (const float*)d_in[5];
    const float* b1   = (const float*)d_in[6];
    const float* W2   = (const float*)d_in[7];
    const float* b2   = (const float*)d_in[8];
    float* out = (float*)d_out;

    const int smem128 = (128 * (128 + 8) + 64 * 132) * 4;   // 103,424 B
    const int smem64  = (128 * ( 64 + 8) + 64 * 132) * 4;   //  70,656 B
    cudaFuncSetAttribute(gemm_k<128, true, 1>, cudaFuncAttributeMaxDynamicSharedMemorySize, smem128);
    cudaFuncSetAttribute(gemm_k<128, true, 2>, cudaFuncAttributeMaxDynamicSharedMemorySize, smem128);
    cudaFuncSetAttribute(gemm_k< 64, false, 0>, cudaFuncAttributeMaxDynamicSharedMemorySize, smem64);

    const int TB = 256;
    prep_all_k<<<(N * 64 + TB - 1) / TB, TB>>>(feat, W0, W1, W2);
    int eb4 = (E / 4 + TB - 1) / TB;   // 1563 blocks (4 edges/thread)
    count_k<<<eb4, TB>>>(dst);
    scanA_k<<<NBLK, SCAN_B>>>();
    scanB_k<<<1, 64>>>();
    scanC_k<<<NBLK, SCAN_B>>>();
    scatter_k<<<eb4, TB>>>(src, dst);

    int ablocks = (N + 15) / 16;     // 3125 (1 node/warp, 16 warps/block)
    int gblocks = (N + 63) / 64;     // 782

    // layer 0: gather bf16 feat (g_bA) -> mean; self = fp32 feat; out g_h0 + shadow g_bB
    agg_k<<<ablocks, 512>>>(0);
    gemm_k<128, true, 1><<<gblocks, TB, smem128>>>(feat, 0, b0, nullptr, 1, 0);
    // layer 1: gather g_bB -> mean; self = g_h0; out g_h1 + shadow g_bA
    agg_k<<<ablocks, 512>>>(1);
    gemm_k<128, true, 2><<<gblocks, TB, smem128>>>(nullptr, 1, b1, nullptr, 2, 1);
    // layer 2: gather g_bA -> mean; self = g_h1; out = dout
    agg_k<<<ablocks, 512>>>(0);
    gemm_k< 64, false, 0><<<gblocks, TB, smem64>>>(nullptr, 2, b2, out, 0, 2);
}

// round 12
// speedup vs baseline: 1.0854x; 1.0854x over previous
#include <cuda_runtime.h>
#include <cuda_bf16.h>
#include <cstdint>

static constexpr int N = 50000;
static constexpr int E = 1600000;
static constexpr int SCAN_B = 1024;
static constexpr int NBLK = (N + SCAN_B - 1) / SCAN_B;   // 49

// ---------------- scratch -----------------------------------------------------
__device__ __align__(16) float g_h0[N * 128];
__device__ __align__(16) float g_h1[N * 128];
__device__ __align__(16) float g_mean[N * 128];
__device__ __align__(16) __nv_bfloat16 g_bA[N * 128];   // bf16 shadows for gather
__device__ __align__(16) __nv_bfloat16 g_bB[N * 128];
__device__ __align__(16) float g_Wr0[256 * 128];        // tf32-rounded, [k][n]
__device__ __align__(16) float g_Wr1[256 * 128];
__device__ __align__(16) float g_Wr2[256 * 64];
__device__ int   g_deg[N];
__device__ int   g_row[N + 1];
__device__ int   g_fill[N];
__device__ int   g_csr[E];
__device__ float g_inv[N];
__device__ int   g_bsum[NBLK];

// cvt.rna.tf32.f32 needs a .b32 destination -> go through a uint register.
__device__ __forceinline__ float to_tf32(float x) {
    uint32_t u;
    asm("cvt.rna.tf32.f32 %0, %1;" : "=r"(u) : "f"(x));
    return __uint_as_float(u);
}
// L2-only load (skip L1 allocation; gather rows have ~0% L1 hit rate)
__device__ __forceinline__ uint2 ldcg_u2(const void* p) {
    uint2 r;
    asm volatile("ld.global.cg.v2.u32 {%0,%1}, [%2];" : "=r"(r.x), "=r"(r.y) : "l"(p));
    return r;
}

// ---------------- merged prep: zero deg + tf32 weights + bf16 features --------
__global__ void prep_all_k(const float* __restrict__ f,
                           const float* __restrict__ W0,
                           const float* __restrict__ W1,
                           const float* __restrict__ W2) {
    int i = blockIdx.x * blockDim.x + threadIdx.x;
    if (i < N * 64) {
        float2 v = ((const float2*)f)[i];
        ((__nv_bfloat162*)g_bA)[i] = __float22bfloat162_rn(v);
    }
    if (i < N) g_deg[i] = 0;
    if (i < 256 * 128) {
        g_Wr0[i] = to_tf32(W0[i]);
        g_Wr1[i] = to_tf32(W1[i]);
    }
    if (i < 256 * 64) g_Wr2[i] = to_tf32(W2[i]);
}

// ---------------- CSR build ---------------------------------------------------
__global__ void count_k(const int* __restrict__ dst) {
    int i = blockIdx.x * blockDim.x + threadIdx.x;
    if (i < E) atomicAdd(&g_deg[dst[i]], 1);
}

// block-local exclusive scan of g_deg -> g_row (no global offset); block sums
__global__ void __launch_bounds__(SCAN_B) scanA_k() {
    __shared__ int wsum[32];
    int tid = threadIdx.x, lane = tid & 31, wid = tid >> 5;
    int i = blockIdx.x * SCAN_B + tid;
    int v = (i < N) ? g_deg[i] : 0;
    int x = v;
    #pragma unroll
    for (int o = 1; o < 32; o <<= 1) {
        int t = __shfl_up_sync(0xffffffffu, x, o);
        if (lane >= o) x += t;
    }
    if (lane == 31) wsum[wid] = x;
    __syncthreads();
    if (wid == 0) {
        int s = wsum[lane];
        #pragma unroll
        for (int o = 1; o < 32; o <<= 1) {
            int t = __shfl_up_sync(0xffffffffu, s, o);
            if (lane >= o) s += t;
        }
        wsum[lane] = s;
    }
    __syncthreads();
    int excl = x - v + (wid ? wsum[wid - 1] : 0);
    if (i < N) g_row[i] = excl;
    if (tid == SCAN_B - 1) g_bsum[blockIdx.x] = wsum[31];
}

// scanC: each block redundantly prefixes the 49 block sums in smem (cheap,
// fully parallel across blocks) -> no separate scanB launch. g_row[N] = E.
__global__ void __launch_bounds__(SCAN_B) scanC_k() {
    __shared__ int pre[NBLK];
    int tid = threadIdx.x;
    if (tid < NBLK) pre[tid] = g_bsum[tid];
    __syncthreads();
    if (tid == 0) {
        int run = 0;
        #pragma unroll 7
        for (int b = 0; b < NBLK; b++) {
            int v = pre[b];
            pre[b] = run;
            run += v;
        }
    }
    __syncthreads();
    int i = blockIdx.x * SCAN_B + tid;
    if (i < N) {
        int r = g_row[i] + pre[blockIdx.x];
        g_row[i] = r;
        g_fill[i] = r;
        int d = g_deg[i];
        g_inv[i] = 1.0f / (float)(d > 0 ? d : 1);
    }
    if (blockIdx.x == 0 && tid == 0) g_row[N] = E;
}

__global__ void scatter_k(const int* __restrict__ src, const int* __restrict__ dst) {
    int i = blockIdx.x * blockDim.x + threadIdx.x;
    if (i < E) {
        int pos = atomicAdd(&g_fill[dst[i]], 1);
        g_csr[pos] = src[i];
    }
}

// ---------------- aggregation: mean of bf16 h[src] over in-edges --------------
// One node per warp; lane covers 4 features. 16-deep unroll -> 16 outstanding
// L2 loads per dependency step. (R9 configuration: 256-thread blocks.)
__global__ void __launch_bounds__(256)
agg_k(int gat_sel) {
    const __nv_bfloat16* h = (gat_sel == 0) ? g_bA : g_bB;
    int tid = threadIdx.x, lane = tid & 31, w = tid >> 5;
    int node = blockIdx.x * 8 + w;
    if (node >= N) return;
    int k4 = lane * 4;
    float4 acc = make_float4(0.f, 0.f, 0.f, 0.f);
    int beg = g_row[node], end = g_row[node + 1];
    int e = beg;
    for (; e + 16 <= end; e += 16) {
        int s[16];
        #pragma unroll
        for (int q = 0; q < 16; q++) s[q] = g_csr[e + q];
        uint2 r[16];
        #pragma unroll
        for (int q = 0; q < 16; q++) r[q] = ldcg_u2(h + s[q] * 128 + k4);
        float x0 = 0.f, y0 = 0.f, z0 = 0.f, w0 = 0.f;
        #pragma unroll
        for (int q = 0; q < 16; q++) {
            x0 += __uint_as_float(r[q].x << 16);
            y0 += __uint_as_float(r[q].x & 0xffff0000u);
            z0 += __uint_as_float(r[q].y << 16);
            w0 += __uint_as_float(r[q].y & 0xffff0000u);
        }
        acc.x += x0; acc.y += y0; acc.z += z0; acc.w += w0;
    }
    for (; e + 4 <= end; e += 4) {
        int s[4];
        #pragma unroll
        for (int q = 0; q < 4; q++) s[q] = g_csr[e + q];
        uint2 r[4];
        #pragma unroll
        for (int q = 0; q < 4; q++) r[q] = ldcg_u2(h + s[q] * 128 + k4);
        #pragma unroll
        for (int q = 0; q < 4; q++) {
            acc.x += __uint_as_float(r[q].x << 16);
            acc.y += __uint_as_float(r[q].x & 0xffff0000u);
            acc.z += __uint_as_float(r[q].y << 16);
            acc.w += __uint_as_float(r[q].y & 0xffff0000u);
        }
    }
    for (; e < end; ++e) {
        int s = g_csr[e];
        uint2 r = ldcg_u2(h + s * 128 + k4);
        acc.x += __uint_as_float(r.x << 16);
        acc.y += __uint_as_float(r.x & 0xffff0000u);
        acc.z += __uint_as_float(r.y << 16);
        acc.w += __uint_as_float(r.y & 0xffff0000u);
    }
    float idg = g_inv[node];
    acc.x *= idg; acc.y *= idg; acc.z *= idg; acc.w *= idg;
    *(float4*)(g_mean + node * 128 + k4) = acc;
}

// ---------------- tf32 mma.sync GEMM layer ------------------------------------
template <int FOUT, bool RELU, int SHADOW>   // SHADOW: 0 none, 1 g_bB, 2 g_bA
__global__ void __launch_bounds__(256)
gemm_k(const float* __restrict__ hself_p, int self_sel,
       const float* __restrict__ bias,
       float* __restrict__ out_p, int out_sel, int wsel) {
    const float* hs = (self_sel == 0) ? hself_p : (self_sel == 1 ? g_h0 : g_h1);
    float* of = (out_sel == 0) ? out_p : (out_sel == 1 ? g_h0 : g_h1);
    const float* Wr = (wsel == 0) ? g_Wr0 : (wsel == 1 ? g_Wr1 : g_Wr2);
    __nv_bfloat16* sh = (SHADOW == 1) ? g_bB : g_bA;

    constexpr int WP = FOUT + 8;
    constexpr int AP = 132;
    constexpr int NT = FOUT / 32;
    extern __shared__ float smem[];
    float* sW = smem;                // [128][WP]
    float* sA = smem + 128 * WP;     // [64][AP]

    int tid = threadIdx.x, lane = tid & 31, w = tid >> 5;
    int g = lane >> 2, tg = lane & 3;
    int wm = w & 1, wn = w >> 1;
    int node_base = blockIdx.x * 64;

    float c[2][NT][4];
    #pragma unroll
    for (int mt = 0; mt < 2; mt++)
        #pragma unroll
        for (int nt = 0; nt < NT; nt++)
            #pragma unroll
            for (int i = 0; i < 4; i++) c[mt][nt][i] = 0.f;

    #pragma unroll
    for (int half = 0; half < 2; half++) {
        const float* srcW = Wr + half * 128 * FOUT;
        for (int idx = tid; idx < 128 * (FOUT / 4); idx += 256) {
            int k = idx / (FOUT / 4);
            int c4 = (idx % (FOUT / 4)) * 4;
            float4 v = *(const float4*)(srcW + k * FOUT + c4);
            *(float4*)(sW + k * WP + c4) = v;
        }
        const float* srcA = (half == 0) ? hs : g_mean;
        for (int idx = tid; idx < 64 * 32; idx += 256) {
            int r = idx >> 5;
            int c4 = (idx & 31) << 2;
            int node = node_base + r;
            float4 v = make_float4(0.f, 0.f, 0.f, 0.f);
            if (node < N) v = *(const float4*)(srcA + node * 128 + c4);
            v.x = to_tf32(v.x); v.y = to_tf32(v.y);
            v.z = to_tf32(v.z); v.w = to_tf32(v.w);
            *(float4*)(sA + r * AP + c4) = v;
        }
        __syncthreads();

        #pragma unroll 4
        for (int s = 0; s < 16; s++) {
            int k = s * 8;
            uint32_t a[2][4];
            #pragma unroll
            for (int mt = 0; mt < 2; mt++) {
                int r0 = wm * 32 + mt * 16 + g;
                a[mt][0] = __float_as_uint(sA[r0 * AP + k + tg]);
                a[mt][1] = __float_as_uint(sA[(r0 + 8) * AP + k + tg]);
                a[mt][2] = __float_as_uint(sA[r0 * AP + k + tg + 4]);
                a[mt][3] = __float_as_uint(sA[(r0 + 8) * AP + k + tg + 4]);
            }
            #pragma unroll
            for (int nt = 0; nt < NT; nt++) {
                int col = wn * (FOUT / 4) + nt * 8 + g;
                uint32_t b0 = __float_as_uint(sW[(k + tg) * WP + col]);
                uint32_t b1 = __float_as_uint(sW[(k + tg + 4) * WP + col]);
                #pragma unroll
                for (int mt = 0; mt < 2; mt++) {
                    asm volatile(
                        "mma.sync.aligned.m16n8k8.row.col.f32.tf32.tf32.f32 "
                        "{%0,%1,%2,%3}, {%4,%5,%6,%7}, {%8,%9}, {%0,%1,%2,%3};"
                        : "+f"(c[mt][nt][0]), "+f"(c[mt][nt][1]),
                          "+f"(c[mt][nt][2]), "+f"(c[mt][nt][3])
                        : "r"(a[mt][0]), "r"(a[mt][1]), "r"(a[mt][2]), "r"(a[mt][3]),
                          "r"(b0), "r"(b1));
                }
            }
        }
        __syncthreads();
    }

    // ---- epilogue: bias + relu + fp32 store (+ bf16 shadow) ----
    #pragma unroll
    for (int nt = 0; nt < NT; nt++) {
        int col = wn * (FOUT / 4) + nt * 8 + tg * 2;
        float bx = __ldg(bias + col), by = __ldg(bias + col + 1);
        #pragma unroll
        for (int mt = 0; mt < 2; mt++) {
            #pragma unroll
            for (int hrow = 0; hrow < 2; hrow++) {
                int node = node_base + wm * 32 + mt * 16 + g + hrow * 8;
                if (node >= N) continue;
                float ox = c[mt][nt][hrow * 2 + 0] + bx;
                float oy = c[mt][nt][hrow * 2 + 1] + by;
                if (RELU) { ox = fmaxf(ox, 0.f); oy = fmaxf(oy, 0.f); }
                *(float2*)(of + node * FOUT + col) = make_float2(ox, oy);
                if (SHADOW != 0) {
                    __nv_bfloat162 p = __float22bfloat162_rn(make_float2(ox, oy));
                    *(__nv_bfloat162*)(sh + node * 128 + col) = p;
                }
            }
        }
    }
}

// ---------------- launcher ----------------------------------------------------
extern "C" void kernel_launch(void* const* d_in, const int* in_sizes, int n_in,
                              void* d_out, int out_size) {
    const float* feat = (const float*)d_in[0];
    const int*   src  = (const int*)d_in[1];
    const int*   dst  = (const int*)d_in[2];
    const float* W0   = (const float*)d_in[3];
    const float* b0   = (const float*)d_in[4];
    const float* W1   = (const float*)d_in[5];
    const float* b1   = (const float*)d_in[6];
    const float* W2   = (const float*)d_in[7];
    const float* b2   = (const float*)d_in[8];
    float* out = (float*)d_out;

    const int smem128 = (128 * (128 + 8) + 64 * 132) * 4;   // 103,424 B
    const int smem64  = (128 * ( 64 + 8) + 64 * 132) * 4;   //  70,656 B
    cudaFuncSetAttribute(gemm_k<128, true, 1>, cudaFuncAttributeMaxDynamicSharedMemorySize, smem128);
    cudaFuncSetAttribute(gemm_k<128, true, 2>, cudaFuncAttributeMaxDynamicSharedMemorySize, smem128);
    cudaFuncSetAttribute(gemm_k< 64, false, 0>, cudaFuncAttributeMaxDynamicSharedMemorySize, smem64);

    const int TB = 256;
    prep_all_k<<<(N * 64 + TB - 1) / TB, TB>>>(feat, W0, W1, W2);
    count_k<<<(E + TB - 1) / TB, TB>>>(dst);
    scanA_k<<<NBLK, SCAN_B>>>();
    scanC_k<<<NBLK, SCAN_B>>>();
    scatter_k<<<(E + TB - 1) / TB, TB>>>(src, dst);

    int ablocks = (N + 7) / 8;       // 6250 (1 node/warp, 8 warps/block)
    int gblocks = (N + 63) / 64;     // 782

    // layer 0: gather bf16 feat (g_bA) -> mean; self = fp32 feat; out g_h0 + shadow g_bB
    agg_k<<<ablocks, TB>>>(0);
    gemm_k<128, true, 1><<<gblocks, TB, smem128>>>(feat, 0, b0, nullptr, 1, 0);
    // layer 1: gather g_bB -> mean; self = g_h0; out g_h1 + shadow g_bA
    agg_k<<<ablocks, TB>>>(1);
    gemm_k<128, true, 2><<<gblocks, TB, smem128>>>(nullptr, 1, b1, nullptr, 2, 1);
    // layer 2: gather g_bA -> mean; self = g_h1; out = dout
    agg_k<<<ablocks, TB>>>(0);
    gemm_k< 64, false, 0><<<gblocks, TB, smem64>>>(nullptr, 2, b2, out, 0, 2);
}

// round 13
// speedup vs baseline: 1.1130x; 1.0255x over previous
#include <cuda_runtime.h>
#include <cuda_bf16.h>
#include <cstdint>

static constexpr int N = 50000;
static constexpr int E = 1600000;
static constexpr int SCAN_B = 1024;
static constexpr int NBLK = (N + SCAN_B - 1) / SCAN_B;   // 49

// ---------------- scratch -----------------------------------------------------
__device__ __align__(16) float g_h0[N * 128];
__device__ __align__(16) float g_h1[N * 128];
__device__ __align__(16) float g_mean[N * 128];
__device__ __align__(16) __nv_bfloat16 g_bA[N * 128];   // bf16 shadows for gather
__device__ __align__(16) __nv_bfloat16 g_bB[N * 128];
__device__ __align__(16) float g_Wr0[256 * 128];        // tf32-rounded, [k][n]
__device__ __align__(16) float g_Wr1[256 * 128];
__device__ __align__(16) float g_Wr2[256 * 64];
__device__ int   g_deg[N];     // zero at start of every call (zero-init + scanC re-zero)
__device__ int   g_row[N + 1];
__device__ int   g_fill[N];
__device__ int   g_csr[E];
__device__ float g_inv[N];
__device__ int   g_bsum[NBLK];

// cvt.rna.tf32.f32 needs a .b32 destination -> go through a uint register.
__device__ __forceinline__ float to_tf32(float x) {
    uint32_t u;
    asm("cvt.rna.tf32.f32 %0, %1;" : "=r"(u) : "f"(x));
    return __uint_as_float(u);
}
// Read-only-cache load (L1-cached __ldg path; rows have reuse ~ out-degree)
__device__ __forceinline__ uint2 ldnc_u2(const void* p) {
    uint2 r;
    asm volatile("ld.global.nc.v2.u32 {%0,%1}, [%2];" : "=r"(r.x), "=r"(r.y) : "l"(p));
    return r;
}

// ---------------- merged prep + degree count ----------------------------------
// g_deg is guaranteed zero on entry (module zero-init on first call; scanC_k
// re-zeroes it at the end of every call). Streaming prep work overlaps the
// atomic-floor-bound degree count.
__global__ void prep_count_k(const float* __restrict__ f,
                             const float* __restrict__ W0,
                             const float* __restrict__ W1,
                             const float* __restrict__ W2,
                             const int* __restrict__ dst) {
    int i = blockIdx.x * blockDim.x + threadIdx.x;
    if (i < E) atomicAdd(&g_deg[dst[i]], 1);
    if (i < N * 64) {
        float2 v = ((const float2*)f)[i];
        ((__nv_bfloat162*)g_bA)[i] = __float22bfloat162_rn(v);
    }
    if (i < 256 * 128) {
        g_Wr0[i] = to_tf32(W0[i]);
        g_Wr1[i] = to_tf32(W1[i]);
    }
    if (i < 256 * 64) g_Wr2[i] = to_tf32(W2[i]);
}

// block-local exclusive scan of g_deg -> g_row (no global offset); block sums
__global__ void __launch_bounds__(SCAN_B) scanA_k() {
    __shared__ int wsum[32];
    int tid = threadIdx.x, lane = tid & 31, wid = tid >> 5;
    int i = blockIdx.x * SCAN_B + tid;
    int v = (i < N) ? g_deg[i] : 0;
    int x = v;
    #pragma unroll
    for (int o = 1; o < 32; o <<= 1) {
        int t = __shfl_up_sync(0xffffffffu, x, o);
        if (lane >= o) x += t;
    }
    if (lane == 31) wsum[wid] = x;
    __syncthreads();
    if (wid == 0) {
        int s = wsum[lane];
        #pragma unroll
        for (int o = 1; o < 32; o <<= 1) {
            int t = __shfl_up_sync(0xffffffffu, s, o);
            if (lane >= o) s += t;
        }
        wsum[lane] = s;
    }
    __syncthreads();
    int excl = x - v + (wid ? wsum[wid - 1] : 0);
    if (i < N) g_row[i] = excl;
    if (tid == SCAN_B - 1) g_bsum[blockIdx.x] = wsum[31];
}

// scanC: per-block redundant prefix of the 49 block sums; writes row/fill/inv
// and RE-ZEROES g_deg so the next call starts clean (graph-replay safe).
__global__ void __launch_bounds__(SCAN_B) scanC_k() {
    __shared__ int pre[NBLK];
    int tid = threadIdx.x;
    if (tid < NBLK) pre[tid] = g_bsum[tid];
    __syncthreads();
    if (tid == 0) {
        int run = 0;
        #pragma unroll 7
        for (int b = 0; b < NBLK; b++) {
            int v = pre[b];
            pre[b] = run;
            run += v;
        }
    }
    __syncthreads();
    int i = blockIdx.x * SCAN_B + tid;
    if (i < N) {
        int r = g_row[i] + pre[blockIdx.x];
        g_row[i] = r;
        g_fill[i] = r;
        int d = g_deg[i];
        g_inv[i] = 1.0f / (float)(d > 0 ? d : 1);
        g_deg[i] = 0;                     // reset for next call
    }
    if (blockIdx.x == 0 && tid == 0) g_row[N] = E;
}

__global__ void scatter_k(const int* __restrict__ src, const int* __restrict__ dst) {
    int i = blockIdx.x * blockDim.x + threadIdx.x;
    if (i < E) {
        int pos = atomicAdd(&g_fill[dst[i]], 1);
        g_csr[pos] = src[i];
    }
}

// ---------------- aggregation: mean of bf16 h[src] over in-edges --------------
// One node per warp; lane covers 4 features. 16-deep unroll -> 16 outstanding
// loads per dependency step. Loads use the read-only L1 path (.nc).
__global__ void __launch_bounds__(256)
agg_k(int gat_sel) {
    const __nv_bfloat16* h = (gat_sel == 0) ? g_bA : g_bB;
    int tid = threadIdx.x, lane = tid & 31, w = tid >> 5;
    int node = blockIdx.x * 8 + w;
    if (node >= N) return;
    int k4 = lane * 4;
    float4 acc = make_float4(0.f, 0.f, 0.f, 0.f);
    int beg = g_row[node], end = g_row[node + 1];
    int e = beg;
    for (; e + 16 <= end; e += 16) {
        int s[16];
        #pragma unroll
        for (int q = 0; q < 16; q++) s[q] = g_csr[e + q];
        uint2 r[16];
        #pragma unroll
        for (int q = 0; q < 16; q++) r[q] = ldnc_u2(h + s[q] * 128 + k4);
        float x0 = 0.f, y0 = 0.f, z0 = 0.f, w0 = 0.f;
        #pragma unroll
        for (int q = 0; q < 16; q++) {
            x0 += __uint_as_float(r[q].x << 16);
            y0 += __uint_as_float(r[q].x & 0xffff0000u);
            z0 += __uint_as_float(r[q].y << 16);
            w0 += __uint_as_float(r[q].y & 0xffff0000u);
        }
        acc.x += x0; acc.y += y0; acc.z += z0; acc.w += w0;
    }
    for (; e + 4 <= end; e += 4) {
        int s[4];
        #pragma unroll
        for (int q = 0; q < 4; q++) s[q] = g_csr[e + q];
        uint2 r[4];
        #pragma unroll
        for (int q = 0; q < 4; q++) r[q] = ldnc_u2(h + s[q] * 128 + k4);
        #pragma unroll
        for (int q = 0; q < 4; q++) {
            acc.x += __uint_as_float(r[q].x << 16);
            acc.y += __uint_as_float(r[q].x & 0xffff0000u);
            acc.z += __uint_as_float(r[q].y << 16);
            acc.w += __uint_as_float(r[q].y & 0xffff0000u);
        }
    }
    for (; e < end; ++e) {
        int s = g_csr[e];
        uint2 r = ldnc_u2(h + s * 128 + k4);
        acc.x += __uint_as_float(r.x << 16);
        acc.y += __uint_as_float(r.x & 0xffff0000u);
        acc.z += __uint_as_float(r.y << 16);
        acc.w += __uint_as_float(r.y & 0xffff0000u);
    }
    float idg = g_inv[node];
    acc.x *= idg; acc.y *= idg; acc.z *= idg; acc.w *= idg;
    *(float4*)(g_mean + node * 128 + k4) = acc;
}

// ---------------- tf32 mma.sync GEMM layer ------------------------------------
template <int FOUT, bool RELU, int SHADOW>   // SHADOW: 0 none, 1 g_bB, 2 g_bA
__global__ void __launch_bounds__(256)
gemm_k(const float* __restrict__ hself_p, int self_sel,
       const float* __restrict__ bias,
       float* __restrict__ out_p, int out_sel, int wsel) {
    const float* hs = (self_sel == 0) ? hself_p : (self_sel == 1 ? g_h0 : g_h1);
    float* of = (out_sel == 0) ? out_p : (out_sel == 1 ? g_h0 : g_h1);
    const float* Wr = (wsel == 0) ? g_Wr0 : (wsel == 1 ? g_Wr1 : g_Wr2);
    __nv_bfloat16* sh = (SHADOW == 1) ? g_bB : g_bA;

    constexpr int WP = FOUT + 8;
    constexpr int AP = 132;
    constexpr int NT = FOUT / 32;
    extern __shared__ float smem[];
    float* sW = smem;                // [128][WP]
    float* sA = smem + 128 * WP;     // [64][AP]

    int tid = threadIdx.x, lane = tid & 31, w = tid >> 5;
    int g = lane >> 2, tg = lane & 3;
    int wm = w & 1, wn = w >> 1;
    int node_base = blockIdx.x * 64;

    float c[2][NT][4];
    #pragma unroll
    for (int mt = 0; mt < 2; mt++)
        #pragma unroll
        for (int nt = 0; nt < NT; nt++)
            #pragma unroll
            for (int i = 0; i < 4; i++) c[mt][nt][i] = 0.f;

    #pragma unroll
    for (int half = 0; half < 2; half++) {
        const float* srcW = Wr + half * 128 * FOUT;
        for (int idx = tid; idx < 128 * (FOUT / 4); idx += 256) {
            int k = idx / (FOUT / 4);
            int c4 = (idx % (FOUT / 4)) * 4;
            float4 v = *(const float4*)(srcW + k * FOUT + c4);
            *(float4*)(sW + k * WP + c4) = v;
        }
        const float* srcA = (half == 0) ? hs : g_mean;
        for (int idx = tid; idx < 64 * 32; idx += 256) {
            int r = idx >> 5;
            int c4 = (idx & 31) << 2;
            int node = node_base + r;
            float4 v = make_float4(0.f, 0.f, 0.f, 0.f);
            if (node < N) v = *(const float4*)(srcA + node * 128 + c4);
            v.x = to_tf32(v.x); v.y = to_tf32(v.y);
            v.z = to_tf32(v.z); v.w = to_tf32(v.w);
            *(float4*)(sA + r * AP + c4) = v;
        }
        __syncthreads();

        #pragma unroll 4
        for (int s = 0; s < 16; s++) {
            int k = s * 8;
            uint32_t a[2][4];
            #pragma unroll
            for (int mt = 0; mt < 2; mt++) {
                int r0 = wm * 32 + mt * 16 + g;
                a[mt][0] = __float_as_uint(sA[r0 * AP + k + tg]);
                a[mt][1] = __float_as_uint(sA[(r0 + 8) * AP + k + tg]);
                a[mt][2] = __float_as_uint(sA[r0 * AP + k + tg + 4]);
                a[mt][3] = __float_as_uint(sA[(r0 + 8) * AP + k + tg + 4]);
            }
            #pragma unroll
            for (int nt = 0; nt < NT; nt++) {
                int col = wn * (FOUT / 4) + nt * 8 + g;
                uint32_t b0 = __float_as_uint(sW[(k + tg) * WP + col]);
                uint32_t b1 = __float_as_uint(sW[(k + tg + 4) * WP + col]);
                #pragma unroll
                for (int mt = 0; mt < 2; mt++) {
                    asm volatile(
                        "mma.sync.aligned.m16n8k8.row.col.f32.tf32.tf32.f32 "
                        "{%0,%1,%2,%3}, {%4,%5,%6,%7}, {%8,%9}, {%0,%1,%2,%3};"
                        : "+f"(c[mt][nt][0]), "+f"(c[mt][nt][1]),
                          "+f"(c[mt][nt][2]), "+f"(c[mt][nt][3])
                        : "r"(a[mt][0]), "r"(a[mt][1]), "r"(a[mt][2]), "r"(a[mt][3]),
                          "r"(b0), "r"(b1));
                }
            }
        }
        __syncthreads();
    }

    // ---- epilogue: bias + relu + fp32 store (+ bf16 shadow) ----
    #pragma unroll
    for (int nt = 0; nt < NT; nt++) {
        int col = wn * (FOUT / 4) + nt * 8 + tg * 2;
        float bx = __ldg(bias + col), by = __ldg(bias + col + 1);
        #pragma unroll
        for (int mt = 0; mt < 2; mt++) {
            #pragma unroll
            for (int hrow = 0; hrow < 2; hrow++) {
                int node = node_base + wm * 32 + mt * 16 + g + hrow * 8;
                if (node >= N) continue;
                float ox = c[mt][nt][hrow * 2 + 0] + bx;
                float oy = c[mt][nt][hrow * 2 + 1] + by;
                if (RELU) { ox = fmaxf(ox, 0.f); oy = fmaxf(oy, 0.f); }
                *(float2*)(of + node * FOUT + col) = make_float2(ox, oy);
                if (SHADOW != 0) {
                    __nv_bfloat162 p = __float22bfloat162_rn(make_float2(ox, oy));
                    *(__nv_bfloat162*)(sh + node * 128 + col) = p;
                }
            }
        }
    }
}

// ---------------- launcher ----------------------------------------------------
extern "C" void kernel_launch(void* const* d_in, const int* in_sizes, int n_in,
                              void* d_out, int out_size) {
    const float* feat = (const float*)d_in[0];
    const int*   src  = (const int*)d_in[1];
    const int*   dst  = (const int*)d_in[2];
    const float* W0   = (const float*)d_in[3];
    const float* b0   = (const float*)d_in[4];
    const float* W1   = (const float*)d_in[5];
    const float* b1   = (const float*)d_in[6];
    const float* W2   = (const float*)d_in[7];
    const float* b2   = (const float*)d_in[8];
    float* out = (float*)d_out;

    const int smem128 = (128 * (128 + 8) + 64 * 132) * 4;   // 103,424 B
    const int smem64  = (128 * ( 64 + 8) + 64 * 132) * 4;   //  70,656 B
    cudaFuncSetAttribute(gemm_k<128, true, 1>, cudaFuncAttributeMaxDynamicSharedMemorySize, smem128);
    cudaFuncSetAttribute(gemm_k<128, true, 2>, cudaFuncAttributeMaxDynamicSharedMemorySize, smem128);
    cudaFuncSetAttribute(gemm_k< 64, false, 0>, cudaFuncAttributeMaxDynamicSharedMemorySize, smem64);

    const int TB = 256;
    // prep + degree count in one kernel (g_deg is zero on entry every call)
    prep_count_k<<<(N * 64 + TB - 1) / TB, TB>>>(feat, W0, W1, W2, dst);
    scanA_k<<<NBLK, SCAN_B>>>();
    scanC_k<<<NBLK, SCAN_B>>>();
    scatter_k<<<(E + TB - 1) / TB, TB>>>(src, dst);

    int ablocks = (N + 7) / 8;       // 6250 (1 node/warp, 8 warps/block)
    int gblocks = (N + 63) / 64;     // 782

    // layer 0: gather bf16 feat (g_bA) -> mean; self = fp32 feat; out g_h0 + shadow g_bB
    agg_k<<<ablocks, TB>>>(0);
    gemm_k<128, true, 1><<<gblocks, TB, smem128>>>(feat, 0, b0, nullptr, 1, 0);
    // layer 1: gather g_bB -> mean; self = g_h0; out g_h1 + shadow g_bA
    agg_k<<<ablocks, TB>>>(1);
    gemm_k<128, true, 2><<<gblocks, TB, smem128>>>(nullptr, 1, b1, nullptr, 2, 1);
    // layer 2: gather g_bA -> mean; self = g_h1; out = dout
    agg_k<<<ablocks, TB>>>(0);
    gemm_k< 64, false, 0><<<gblocks, TB, smem64>>>(nullptr, 2, b2, out, 0, 2);
}

// round 14
// speedup vs baseline: 1.1204x; 1.0066x over previous
#include <cuda_runtime.h>
#include <cuda_bf16.h>
#include <cstdint>

static constexpr int N = 50000;
static constexpr int E = 1600000;
static constexpr int SCAN_B = 1024;
static constexpr int NBLK = (N + SCAN_B - 1) / SCAN_B;   // 49

// ---------------- scratch -----------------------------------------------------
__device__ __align__(16) float g_h0[N * 128];   // layer0 out; later reused as z2/y-free scratch
__device__ __align__(16) float g_h1[N * 128];   // layer1 out (self input to layer2)
__device__ __align__(16) float g_mean[N * 128];
__device__ __align__(16) __nv_bfloat16 g_bA[N * 128];   // bf16 feat shadow (layer0 gather)
__device__ __align__(16) __nv_bfloat16 g_bB[N * 128];   // layer0-out shadow; later y2 64-dim shadow
__device__ __align__(16) float g_Wr0[256 * 128];        // tf32-rounded, [k][n]
__device__ __align__(16) float g_Wr1[256 * 128];
__device__ __align__(16) float g_Wr2x[128 * 128];       // [k][ z-cols | y-cols ]
__device__ float g_z[N * 64];                            // z2 = h2 @ W2_top + b
__device__ int   g_deg[N];     // zero at start of every call (zero-init + scanC re-zero)
__device__ int   g_row[N + 1];
__device__ int   g_fill[N];
__device__ int   g_csr[E];
__device__ float g_inv[N];
__device__ int   g_bsum[NBLK];

// cvt.rna.tf32.f32 needs a .b32 destination -> go through a uint register.
__device__ __forceinline__ float to_tf32(float x) {
    uint32_t u;
    asm("cvt.rna.tf32.f32 %0, %1;" : "=r"(u) : "f"(x));
    return __uint_as_float(u);
}
__device__ __forceinline__ uint2 ldnc_u2(const void* p) {
    uint2 r;
    asm volatile("ld.global.nc.v2.u32 {%0,%1}, [%2];" : "=r"(r.x), "=r"(r.y) : "l"(p));
    return r;
}
__device__ __forceinline__ uint32_t ldnc_u1(const void* p) {
    uint32_t r;
    asm volatile("ld.global.nc.u32 %0, [%1];" : "=r"(r) : "l"(p));
    return r;
}

// ---------------- merged prep + degree count ----------------------------------
__global__ void prep_count_k(const float* __restrict__ f,
                             const float* __restrict__ W0,
                             const float* __restrict__ W1,
                             const float* __restrict__ W2,
                             const int* __restrict__ dst) {
    int i = blockIdx.x * blockDim.x + threadIdx.x;
    if (i < E) atomicAdd(&g_deg[dst[i]], 1);
    if (i < N * 64) {
        float2 v = ((const float2*)f)[i];
        ((__nv_bfloat162*)g_bA)[i] = __float22bfloat162_rn(v);
    }
    if (i < 256 * 128) {
        g_Wr0[i] = to_tf32(W0[i]);
        g_Wr1[i] = to_tf32(W1[i]);
    }
    if (i < 128 * 128) {
        // W2 is [256][64]; build W2x[k][n]: n<64 -> W2[k][n] (top), n>=64 -> W2[128+k][n-64] (bottom)
        int k = i >> 7, n = i & 127;
        float v = (n < 64) ? W2[k * 64 + n] : W2[(128 + k) * 64 + (n - 64)];
        g_Wr2x[i] = to_tf32(v);
    }
}

// block-local exclusive scan of g_deg -> g_row; block sums
__global__ void __launch_bounds__(SCAN_B) scanA_k() {
    __shared__ int wsum[32];
    int tid = threadIdx.x, lane = tid & 31, wid = tid >> 5;
    int i = blockIdx.x * SCAN_B + tid;
    int v = (i < N) ? g_deg[i] : 0;
    int x = v;
    #pragma unroll
    for (int o = 1; o < 32; o <<= 1) {
        int t = __shfl_up_sync(0xffffffffu, x, o);
        if (lane >= o) x += t;
    }
    if (lane == 31) wsum[wid] = x;
    __syncthreads();
    if (wid == 0) {
        int s = wsum[lane];
        #pragma unroll
        for (int o = 1; o < 32; o <<= 1) {
            int t = __shfl_up_sync(0xffffffffu, s, o);
            if (lane >= o) s += t;
        }
        wsum[lane] = s;
    }
    __syncthreads();
    int excl = x - v + (wid ? wsum[wid - 1] : 0);
    if (i < N) g_row[i] = excl;
    if (tid == SCAN_B - 1) g_bsum[blockIdx.x] = wsum[31];
}

// scanC: per-block redundant prefix of block sums; writes row/fill/inv; re-zeroes deg
__global__ void __launch_bounds__(SCAN_B) scanC_k() {
    __shared__ int pre[NBLK];
    int tid = threadIdx.x;
    if (tid < NBLK) pre[tid] = g_bsum[tid];
    __syncthreads();
    if (tid == 0) {
        int run = 0;
        #pragma unroll 7
        for (int b = 0; b < NBLK; b++) {
            int v = pre[b];
            pre[b] = run;
            run += v;
        }
    }
    __syncthreads();
    int i = blockIdx.x * SCAN_B + tid;
    if (i < N) {
        int r = g_row[i] + pre[blockIdx.x];
        g_row[i] = r;
        g_fill[i] = r;
        int d = g_deg[i];
        g_inv[i] = 1.0f / (float)(d > 0 ? d : 1);
        g_deg[i] = 0;                     // reset for next call
    }
    if (blockIdx.x == 0 && tid == 0) g_row[N] = E;
}

__global__ void scatter_k(const int* __restrict__ src, const int* __restrict__ dst) {
    int i = blockIdx.x * blockDim.x + threadIdx.x;
    if (i < E) {
        int pos = atomicAdd(&g_fill[dst[i]], 1);
        g_csr[pos] = src[i];
    }
}

// ---------------- aggregation (128-dim bf16 gather -> fp32 mean) --------------
__global__ void __launch_bounds__(256)
agg_k(int gat_sel) {
    const __nv_bfloat16* h = (gat_sel == 0) ? g_bA : g_bB;
    int tid = threadIdx.x, lane = tid & 31, w = tid >> 5;
    int node = blockIdx.x * 8 + w;
    if (node >= N) return;
    int k4 = lane * 4;
    float4 acc = make_float4(0.f, 0.f, 0.f, 0.f);
    int beg = g_row[node], end = g_row[node + 1];
    int e = beg;
    for (; e + 16 <= end; e += 16) {
        int s[16];
        #pragma unroll
        for (int q = 0; q < 16; q++) s[q] = g_csr[e + q];
        uint2 r[16];
        #pragma unroll
        for (int q = 0; q < 16; q++) r[q] = ldnc_u2(h + s[q] * 128 + k4);
        float x0 = 0.f, y0 = 0.f, z0 = 0.f, w0 = 0.f;
        #pragma unroll
        for (int q = 0; q < 16; q++) {
            x0 += __uint_as_float(r[q].x << 16);
            y0 += __uint_as_float(r[q].x & 0xffff0000u);
            z0 += __uint_as_float(r[q].y << 16);
            w0 += __uint_as_float(r[q].y & 0xffff0000u);
        }
        acc.x += x0; acc.y += y0; acc.z += z0; acc.w += w0;
    }
    for (; e + 4 <= end; e += 4) {
        int s[4];
        #pragma unroll
        for (int q = 0; q < 4; q++) s[q] = g_csr[e + q];
        uint2 r[4];
        #pragma unroll
        for (int q = 0; q < 4; q++) r[q] = ldnc_u2(h + s[q] * 128 + k4);
        #pragma unroll
        for (int q = 0; q < 4; q++) {
            acc.x += __uint_as_float(r[q].x << 16);
            acc.y += __uint_as_float(r[q].x & 0xffff0000u);
            acc.z += __uint_as_float(r[q].y << 16);
            acc.w += __uint_as_float(r[q].y & 0xffff0000u);
        }
    }
    for (; e < end; ++e) {
        int s = g_csr[e];
        uint2 r = ldnc_u2(h + s * 128 + k4);
        acc.x += __uint_as_float(r.x << 16);
        acc.y += __uint_as_float(r.x & 0xffff0000u);
        acc.z += __uint_as_float(r.y << 16);
        acc.w += __uint_as_float(r.y & 0xffff0000u);
    }
    float idg = g_inv[node];
    acc.x *= idg; acc.y *= idg; acc.z *= idg; acc.w *= idg;
    *(float4*)(g_mean + node * 128 + k4) = acc;
}

// ---- layer-2 final: 64-dim bf16 gather of y2, fused add with z2 -> out -------
__global__ void __launch_bounds__(256)
agg64_k(float* __restrict__ out) {
    int tid = threadIdx.x, lane = tid & 31, w = tid >> 5;
    int node = blockIdx.x * 8 + w;
    if (node >= N) return;
    int k2 = lane * 2;
    float ax = 0.f, ay = 0.f;
    int beg = g_row[node], end = g_row[node + 1];
    int e = beg;
    for (; e + 16 <= end; e += 16) {
        int s[16];
        #pragma unroll
        for (int q = 0; q < 16; q++) s[q] = g_csr[e + q];
        uint32_t r[16];
        #pragma unroll
        for (int q = 0; q < 16; q++) r[q] = ldnc_u1(g_bB + s[q] * 64 + k2);
        float x0 = 0.f, y0 = 0.f;
        #pragma unroll
        for (int q = 0; q < 16; q++) {
            x0 += __uint_as_float(r[q] << 16);
            y0 += __uint_as_float(r[q] & 0xffff0000u);
        }
        ax += x0; ay += y0;
    }
    for (; e + 4 <= end; e += 4) {
        int s[4];
        #pragma unroll
        for (int q = 0; q < 4; q++) s[q] = g_csr[e + q];
        uint32_t r[4];
        #pragma unroll
        for (int q = 0; q < 4; q++) r[q] = ldnc_u1(g_bB + s[q] * 64 + k2);
        #pragma unroll
        for (int q = 0; q < 4; q++) {
            ax += __uint_as_float(r[q] << 16);
            ay += __uint_as_float(r[q] & 0xffff0000u);
        }
    }
    for (; e < end; ++e) {
        uint32_t r = ldnc_u1(g_bB + g_csr[e] * 64 + k2);
        ax += __uint_as_float(r << 16);
        ay += __uint_as_float(r & 0xffff0000u);
    }
    float idg = g_inv[node];
    float2 z = *(const float2*)(g_z + node * 64 + k2);
    *(float2*)(out + node * 64 + k2) = make_float2(z.x + ax * idg, z.y + ay * idg);
}

// ---------------- tf32 mma.sync GEMM (layers 0,1) -----------------------------
template <int FOUT, bool RELU, int SHADOW>   // SHADOW: 0 none, 1 g_bB
__global__ void __launch_bounds__(256)
gemm_k(const float* __restrict__ hself_p, int self_sel,
       const float* __restrict__ bias,
       int out_sel, int wsel) {
    const float* hs = (self_sel == 0) ? hself_p : g_h0;
    float* of = (out_sel == 1) ? g_h0 : g_h1;
    const float* Wr = (wsel == 0) ? g_Wr0 : g_Wr1;

    constexpr int WP = FOUT + 8;
    constexpr int AP = 132;
    constexpr int NT = FOUT / 32;
    extern __shared__ float smem[];
    float* sW = smem;                // [128][WP]
    float* sA = smem + 128 * WP;     // [64][AP]

    int tid = threadIdx.x, lane = tid & 31, w = tid >> 5;
    int g = lane >> 2, tg = lane & 3;
    int wm = w & 1, wn = w >> 1;
    int node_base = blockIdx.x * 64;

    float c[2][NT][4];
    #pragma unroll
    for (int mt = 0; mt < 2; mt++)
        #pragma unroll
        for (int nt = 0; nt < NT; nt++)
            #pragma unroll
            for (int i = 0; i < 4; i++) c[mt][nt][i] = 0.f;

    #pragma unroll
    for (int half = 0; half < 2; half++) {
        const float* srcW = Wr + half * 128 * FOUT;
        for (int idx = tid; idx < 128 * (FOUT / 4); idx += 256) {
            int k = idx / (FOUT / 4);
            int c4 = (idx % (FOUT / 4)) * 4;
            float4 v = *(const float4*)(srcW + k * FOUT + c4);
            *(float4*)(sW + k * WP + c4) = v;
        }
        const float* srcA = (half == 0) ? hs : g_mean;
        for (int idx = tid; idx < 64 * 32; idx += 256) {
            int r = idx >> 5;
            int c4 = (idx & 31) << 2;
            int node = node_base + r;
            float4 v = make_float4(0.f, 0.f, 0.f, 0.f);
            if (node < N) v = *(const float4*)(srcA + node * 128 + c4);
            v.x = to_tf32(v.x); v.y = to_tf32(v.y);
            v.z = to_tf32(v.z); v.w = to_tf32(v.w);
            *(float4*)(sA + r * AP + c4) = v;
        }
        __syncthreads();

        #pragma unroll 4
        for (int s = 0; s < 16; s++) {
            int k = s * 8;
            uint32_t a[2][4];
            #pragma unroll
            for (int mt = 0; mt < 2; mt++) {
                int r0 = wm * 32 + mt * 16 + g;
                a[mt][0] = __float_as_uint(sA[r0 * AP + k + tg]);
                a[mt][1] = __float_as_uint(sA[(r0 + 8) * AP + k + tg]);
                a[mt][2] = __float_as_uint(sA[r0 * AP + k + tg + 4]);
                a[mt][3] = __float_as_uint(sA[(r0 + 8) * AP + k + tg + 4]);
            }
            #pragma unroll
            for (int nt = 0; nt < NT; nt++) {
                int col = wn * (FOUT / 4) + nt * 8 + g;
                uint32_t b0 = __float_as_uint(sW[(k + tg) * WP + col]);
                uint32_t b1 = __float_as_uint(sW[(k + tg + 4) * WP + col]);
                #pragma unroll
                for (int mt = 0; mt < 2; mt++) {
                    asm volatile(
                        "mma.sync.aligned.m16n8k8.row.col.f32.tf32.tf32.f32 "
                        "{%0,%1,%2,%3}, {%4,%5,%6,%7}, {%8,%9}, {%0,%1,%2,%3};"
                        : "+f"(c[mt][nt][0]), "+f"(c[mt][nt][1]),
                          "+f"(c[mt][nt][2]), "+f"(c[mt][nt][3])
                        : "r"(a[mt][0]), "r"(a[mt][1]), "r"(a[mt][2]), "r"(a[mt][3]),
                          "r"(b0), "r"(b1));
                }
            }
        }
        __syncthreads();
    }

    #pragma unroll
    for (int nt = 0; nt < NT; nt++) {
        int col = wn * (FOUT / 4) + nt * 8 + tg * 2;
        float bx = __ldg(bias + col), by = __ldg(bias + col + 1);
        #pragma unroll
        for (int mt = 0; mt < 2; mt++) {
            #pragma unroll
            for (int hrow = 0; hrow < 2; hrow++) {
                int node = node_base + wm * 32 + mt * 16 + g + hrow * 8;
                if (node >= N) continue;
                float ox = c[mt][nt][hrow * 2 + 0] + bx;
                float oy = c[mt][nt][hrow * 2 + 1] + by;
                if (RELU) { ox = fmaxf(ox, 0.f); oy = fmaxf(oy, 0.f); }
                *(float2*)(of + node * FOUT + col) = make_float2(ox, oy);
                if (SHADOW == 1) {
                    __nv_bfloat162 p = __float22bfloat162_rn(make_float2(ox, oy));
                    *(__nv_bfloat162*)(g_bB + node * 128 + col) = p;
                }
            }
        }
    }
}

// ---------------- layer-2 GEMM: [z2|y2] = h2 @ [W2_top|W2_bot] -----------------
// K=128, FOUT=128. cols 0-63 -> z2 (+bias) fp32 in g_z; cols 64-127 -> y2 bf16 in g_bB (stride 64).
__global__ void __launch_bounds__(256)
gemm2x_k(const float* __restrict__ bias) {
    constexpr int WP = 136;
    constexpr int AP = 132;
    extern __shared__ float smem[];
    float* sW = smem;                // [128][136]
    float* sA = smem + 128 * WP;     // [64][132]

    int tid = threadIdx.x, lane = tid & 31, w = tid >> 5;
    int g = lane >> 2, tg = lane & 3;
    int wm = w & 1, wn = w >> 1;
    int node_base = blockIdx.x * 64;

    float c[2][4][4];
    #pragma unroll
    for (int mt = 0; mt < 2; mt++)
        #pragma unroll
        for (int nt = 0; nt < 4; nt++)
            #pragma unroll
            for (int i = 0; i < 4; i++) c[mt][nt][i] = 0.f;

    for (int idx = tid; idx < 128 * 32; idx += 256) {
        int k = idx >> 5;
        int c4 = (idx & 31) << 2;
        float4 v = *(const float4*)(g_Wr2x + k * 128 + c4);
        *(float4*)(sW + k * WP + c4) = v;
    }
    for (int idx = tid; idx < 64 * 32; idx += 256) {
        int r = idx >> 5;
        int c4 = (idx & 31) << 2;
        int node = node_base + r;
        float4 v = make_float4(0.f, 0.f, 0.f, 0.f);
        if (node < N) v = *(const float4*)(g_h1 + node * 128 + c4);
        v.x = to_tf32(v.x); v.y = to_tf32(v.y);
        v.z = to_tf32(v.z); v.w = to_tf32(v.w);
        *(float4*)(sA + r * AP + c4) = v;
    }
    __syncthreads();

    #pragma unroll 4
    for (int s = 0; s < 16; s++) {
        int k = s * 8;
        uint32_t a[2][4];
        #pragma unroll
        for (int mt = 0; mt < 2; mt++) {
            int r0 = wm * 32 + mt * 16 + g;
            a[mt][0] = __float_as_uint(sA[r0 * AP + k + tg]);
            a[mt][1] = __float_as_uint(sA[(r0 + 8) * AP + k + tg]);
            a[mt][2] = __float_as_uint(sA[r0 * AP + k + tg + 4]);
            a[mt][3] = __float_as_uint(sA[(r0 + 8) * AP + k + tg + 4]);
        }
        #pragma unroll
        for (int nt = 0; nt < 4; nt++) {
            int col = wn * 32 + nt * 8 + g;
            uint32_t b0 = __float_as_uint(sW[(k + tg) * WP + col]);
            uint32_t b1 = __float_as_uint(sW[(k + tg + 4) * WP + col]);
            #pragma unroll
            for (int mt = 0; mt < 2; mt++) {
                asm volatile(
                    "mma.sync.aligned.m16n8k8.row.col.f32.tf32.tf32.f32 "
                    "{%0,%1,%2,%3}, {%4,%5,%6,%7}, {%8,%9}, {%0,%1,%2,%3};"
                    : "+f"(c[mt][nt][0]), "+f"(c[mt][nt][1]),
                      "+f"(c[mt][nt][2]), "+f"(c[mt][nt][3])
                    : "r"(a[mt][0]), "r"(a[mt][1]), "r"(a[mt][2]), "r"(a[mt][3]),
                      "r"(b0), "r"(b1));
            }
        }
    }

    #pragma unroll
    for (int nt = 0; nt < 4; nt++) {
        int col = wn * 32 + nt * 8 + tg * 2;
        bool zcol = (col < 64);
        float bx = zcol ? __ldg(bias + col) : 0.f;
        float by = zcol ? __ldg(bias + col + 1) : 0.f;
        #pragma unroll
        for (int mt = 0; mt < 2; mt++) {
            #pragma unroll
            for (int hrow = 0; hrow < 2; hrow++) {
                int node = node_base + wm * 32 + mt * 16 + g + hrow * 8;
                if (node >= N) continue;
                float ox = c[mt][nt][hrow * 2 + 0] + bx;
                float oy = c[mt][nt][hrow * 2 + 1] + by;
                if (zcol) {
                    *(float2*)(g_z + node * 64 + col) = make_float2(ox, oy);
                } else {
                    __nv_bfloat162 p = __float22bfloat162_rn(make_float2(ox, oy));
                    *(__nv_bfloat162*)(g_bB + node * 64 + (col - 64)) = p;
                }
            }
        }
    }
}

// ---------------- launcher ----------------------------------------------------
extern "C" void kernel_launch(void* const* d_in, const int* in_sizes, int n_in,
                              void* d_out, int out_size) {
    const float* feat = (const float*)d_in[0];
    const int*   src  = (const int*)d_in[1];
    const int*   dst  = (const int*)d_in[2];
    const float* W0   = (const float*)d_in[3];
    const float* b0   = (const float*)d_in[4];
    const float* W1   = (const float*)d_in[5];
    const float* b1   = (const float*)d_in[6];
    const float* W2   = (const float*)d_in[7];
    const float* b2   = (const float*)d_in[8];
    float* out = (float*)d_out;

    const int smem128 = (128 * 136 + 64 * 132) * 4;   // 103,424 B
    cudaFuncSetAttribute(gemm_k<128, true, 1>, cudaFuncAttributeMaxDynamicSharedMemorySize, smem128);
    cudaFuncSetAttribute(gemm_k<128, true, 0>, cudaFuncAttributeMaxDynamicSharedMemorySize, smem128);
    cudaFuncSetAttribute(gemm2x_k, cudaFuncAttributeMaxDynamicSharedMemorySize, smem128);

    const int TB = 256;
    prep_count_k<<<(N * 64 + TB - 1) / TB, TB>>>(feat, W0, W1, W2, dst);
    scanA_k<<<NBLK, SCAN_B>>>();
    scanC_k<<<NBLK, SCAN_B>>>();
    scatter_k<<<(E + TB - 1) / TB, TB>>>(src, dst);

    int ablocks = (N + 7) / 8;       // 6250 (1 node/warp)
    int gblocks = (N + 63) / 64;     // 782

    // layer 0: gather bf16 feat (g_bA); self = fp32 feat; out g_h0 + shadow g_bB
    agg_k<<<ablocks, TB>>>(0);
    gemm_k<128, true, 1><<<gblocks, TB, smem128>>>(feat, 0, b0, 1, 0);
    // layer 1: gather g_bB (layer0 shadow); self = g_h0; out g_h1 (no shadow needed)
    agg_k<<<ablocks, TB>>>(1);
    gemm_k<128, true, 0><<<gblocks, TB, smem128>>>(nullptr, 1, b1, 2, 1);
    // layer 2 (projection-first): [z2|y2] = h2 @ [W2_top|W2_bot]; then 64-dim gather + fused add
    gemm2x_k<<<gblocks, TB, smem128>>>(b2);
    agg64_k<<<ablocks, TB>>>(out);
}